// round 13
// baseline (speedup 1.0000x reference)
#include <cuda_runtime.h>
#include <cstdint>

// x (8, 3, 65536) f32 -> out (8, 3, 512) f32, farthest point sampling.
// R12 skeleton (== R5 perf) + latency-tree max/min accumulators in compute.
#define BATCHES 8
#define NPTS    65536
#define MOUT    512
#define CLUSTER 8                         // CTAs per batch (one cluster)
#define TPB     256
#define TPBATCH (CLUSTER * TPB)           // 2048 threads per batch
#define PPT     (NPTS / TPBATCH)          // 32 points per thread (register-resident)
#define PAIRS   (PPT / 2)                 // 16 packed f32x2 pairs

typedef unsigned long long u64;
typedef unsigned int u32;

// ---- cluster helpers ----
__device__ __forceinline__ u32 cluster_rank() {
    u32 r; asm("mov.u32 %0, %%cluster_ctarank;" : "=r"(r)); return r;
}
__device__ __forceinline__ u32 smem_u32(const void* p) {
    return (u32)__cvta_generic_to_shared(p);
}
__device__ __forceinline__ void cluster_sync_all() {
    asm volatile("barrier.cluster.arrive.aligned;" ::: "memory");
    asm volatile("barrier.cluster.wait.aligned;"   ::: "memory");
}
// ---- packed f32x2 math (per-lane IEEE .rn, bit-identical to scalar) ----
__device__ __forceinline__ u64 f2pack(float lo, float hi) {
    u64 r; asm("mov.b64 %0, {%1, %2};" : "=l"(r) : "f"(lo), "f"(hi)); return r;
}
__device__ __forceinline__ void f2unpack(float& lo, float& hi, u64 v) {
    asm("mov.b64 {%0, %1}, %2;" : "=f"(lo), "=f"(hi) : "l"(v));
}
__device__ __forceinline__ u64 f2add(u64 a, u64 b) {
    u64 r; asm("add.rn.f32x2 %0, %1, %2;" : "=l"(r) : "l"(a), "l"(b)); return r;
}
__device__ __forceinline__ u64 f2mul(u64 a, u64 b) {
    u64 r; asm("mul.rn.f32x2 %0, %1, %2;" : "=l"(r) : "l"(a), "l"(b)); return r;
}

__global__ void __launch_bounds__(TPB, 1) __cluster_dims__(CLUSTER, 1, 1)
fps_kernel(const float* __restrict__ x, float* __restrict__ out)
{
    __shared__ u64 s_wkey[TPB / 32];        // per-warp winners
    __shared__ u64 s_cand[2][CLUSTER];      // double-buffered cluster candidates

    const u32 rank = cluster_rank();
    const int b    = blockIdx.x / CLUSTER;
    const int tid  = threadIdx.x;
    const int lane = tid & 31;
    const int warp = tid >> 5;
    const int tcl  = (int)rank * TPB + tid;                // 0..2047 within batch

    const float* __restrict__ xb = x + (size_t)b * 3 * NPTS;
    float* __restrict__ ob       = out + (size_t)b * 3 * MOUT;

    // Register-resident points (packed pairs) + running min distance
    u64 px2[PAIRS], py2[PAIRS], pz2[PAIRS];
    float dist[PPT];
#pragma unroll
    for (int i = 0; i < PAIRS; i++) {
        int k0 = 2 * i, k1 = 2 * i + 1;
        int g0 = k0 * TPBATCH + tcl, g1 = k1 * TPBATCH + tcl;   // coalesced
        px2[i] = f2pack(__ldg(xb + g0),            __ldg(xb + g1));
        py2[i] = f2pack(__ldg(xb + NPTS + g0),     __ldg(xb + NPTS + g1));
        pz2[i] = f2pack(__ldg(xb + 2 * NPTS + g0), __ldg(xb + 2 * NPTS + g1));
        dist[k0] = INFINITY;
        dist[k1] = INFINITY;
    }

    // First centroid is point 0 (standard PointNet++ convention)
    float cx = __ldg(xb);
    float cy = __ldg(xb + NPTS);
    float cz = __ldg(xb + 2 * NPTS);
    if (rank == 0 && tid == 0) {
        ob[0]        = cx;
        ob[MOUT]     = cy;
        ob[2 * MOUT] = cz;
    }

    for (int j = 1; j < MOUT; j++) {
        // ---- pass 1: packed distance update. Per-lane .rn arithmetic, same
        //      order as reference: (dx*dx + dy*dy) + dz*dz.
        //      Max tracked in 4 INDEPENDENT accumulators (fmax is exact and
        //      associative -> bit-identical 'best', ~1/4 the RAW chain depth).
        u64 ncx = f2pack(-cx, -cx);
        u64 ncy = f2pack(-cy, -cy);
        u64 ncz = f2pack(-cz, -cz);
        float b0 = -1.0f, b1 = -1.0f, b2 = -1.0f, b3 = -1.0f;
#pragma unroll
        for (int i = 0; i < PAIRS; i++) {
            u64 dx = f2add(px2[i], ncx);
            u64 dy = f2add(py2[i], ncy);
            u64 dz = f2add(pz2[i], ncz);
            u64 s  = f2add(f2mul(dx, dx), f2mul(dy, dy));
            u64 dd = f2add(s, f2mul(dz, dz));
            float e0, e1;
            f2unpack(e0, e1, dd);
            float n0 = fminf(dist[2 * i],     e0);
            float n1 = fminf(dist[2 * i + 1], e1);
            dist[2 * i]     = n0;
            dist[2 * i + 1] = n1;
            if (i & 1) { b2 = fmaxf(b2, n0); b3 = fmaxf(b3, n1); }
            else       { b0 = fmaxf(b0, n0); b1 = fmaxf(b1, n1); }
        }
        float best = fmaxf(fmaxf(b0, b1), fmaxf(b2, b3));

        // ---- pass 2: min k among dist[k]==best, 4 independent min chains
        //      (integer min reorder is exact; first-occurrence preserved) ----
        int ka = 0x7FFFFFFF, kbb = 0x7FFFFFFF, kc = 0x7FFFFFFF, kd = 0x7FFFFFFF;
#pragma unroll
        for (int k = 0; k < PPT; k += 4) {
            if (dist[k]     == best) ka  = min(ka,  k);
            if (dist[k + 1] == best) kbb = min(kbb, k + 1);
            if (dist[k + 2] == best) kc  = min(kc,  k + 2);
            if (dist[k + 3] == best) kd  = min(kd,  k + 3);
        }
        int kb = min(min(ka, kbb), min(kc, kd));
        int bidx = kb * TPBATCH + tcl;

        // Packed key: (dist bits << 32) | ~idx  -> max picks largest dist,
        // ties resolved to the LOWEST index (jnp.argmax first-occurrence).
        u64 key = ((u64)__float_as_uint(best) << 32) |
                  (u64)(u32)(~(u32)bidx);

        // ---- warp reduce (proven shuffle chain) ----
#pragma unroll
        for (int off = 16; off > 0; off >>= 1) {
            u64 k2 = __shfl_down_sync(0xFFFFFFFFu, key, off);
            if (k2 > key) key = k2;
        }
        if (lane == 0) s_wkey[warp] = key;
        __syncthreads();

        // ---- block reduce: warp 0 butterfly (lanes 0..7 all end holding the
        //      block winner); lanes 0..7 fan it out to all 8 ranks in parallel ----
        if (warp == 0) {
            u64 bk = s_wkey[lane & 7];
#pragma unroll
            for (int off = 4; off > 0; off >>= 1) {
                u64 k2 = __shfl_xor_sync(0xFFFFFFFFu, bk, off);
                if (k2 > bk) bk = k2;
            }
            if (lane < CLUSTER) {
                u32 laddr = smem_u32(&s_cand[j & 1][rank]);
                u32 dst;
                asm volatile("mapa.shared::cluster.u32 %0, %1, %2;"
                             : "=r"(dst) : "r"(laddr), "r"((u32)lane));
                asm volatile("st.shared::cluster.u64 [%0], %1;"
                             :: "r"(dst), "l"(bk) : "memory");
            }
        }

        // ---- cluster barrier (arrive=release / wait=acquire orders the
        //      DSMEM stores above against the local reads below) ----
        cluster_sync_all();

        // ---- pick global winner from 8 local candidates (pairwise tree) ----
        {
            const u64* cand = s_cand[j & 1];
            u64 m0 = cand[0], m1 = cand[1], m2 = cand[2], m3 = cand[3];
            u64 m4 = cand[4], m5 = cand[5], m6 = cand[6], m7 = cand[7];
            u64 a = (m1 > m0) ? m1 : m0;
            u64 c = (m3 > m2) ? m3 : m2;
            u64 e = (m5 > m4) ? m5 : m4;
            u64 g = (m7 > m6) ? m7 : m6;
            u64 ac = (c > a) ? c : a;
            u64 eg = (g > e) ? g : e;
            u64 wk = (eg > ac) ? eg : ac;
            int widx = (int)(~(u32)wk);

            // ---- fetch winning centroid coords (L2-resident broadcast load) ----
            cx = __ldg(xb + widx);
            cy = __ldg(xb + NPTS + widx);
            cz = __ldg(xb + 2 * NPTS + widx);
        }

        if (rank == 0 && tid == 0) {
            ob[j]            = cx;
            ob[MOUT + j]     = cy;
            ob[2 * MOUT + j] = cz;
        }
    }
}

extern "C" void kernel_launch(void* const* d_in, const int* in_sizes, int n_in,
                              void* d_out, int out_size)
{
    const float* x = (const float*)d_in[0];
    float* out     = (float*)d_out;
    fps_kernel<<<BATCHES * CLUSTER, TPB>>>(x, out);
}

// round 14
// speedup vs baseline: 1.1024x; 1.1024x over previous
#include <cuda_runtime.h>
#include <cstdint>

// x (8, 3, 65536) f32 -> out (8, 3, 512) f32, farthest point sampling.
// R12 skeleton + REDUX reductions (R6/R10-proven numerics) in both stages.
#define BATCHES 8
#define NPTS    65536
#define MOUT    512
#define CLUSTER 8                         // CTAs per batch (one cluster)
#define TPB     256
#define TPBATCH (CLUSTER * TPB)           // 2048 threads per batch
#define PPT     (NPTS / TPBATCH)          // 32 points per thread (register-resident)
#define PAIRS   (PPT / 2)                 // 16 packed f32x2 pairs

typedef unsigned long long u64;
typedef unsigned int u32;

// ---- cluster helpers ----
__device__ __forceinline__ u32 cluster_rank() {
    u32 r; asm("mov.u32 %0, %%cluster_ctarank;" : "=r"(r)); return r;
}
__device__ __forceinline__ u32 smem_u32(const void* p) {
    return (u32)__cvta_generic_to_shared(p);
}
__device__ __forceinline__ void cluster_sync_all() {
    asm volatile("barrier.cluster.arrive.aligned;" ::: "memory");
    asm volatile("barrier.cluster.wait.aligned;"   ::: "memory");
}
// ---- packed f32x2 math (per-lane IEEE .rn, bit-identical to scalar) ----
__device__ __forceinline__ u64 f2pack(float lo, float hi) {
    u64 r; asm("mov.b64 %0, {%1, %2};" : "=l"(r) : "f"(lo), "f"(hi)); return r;
}
__device__ __forceinline__ void f2unpack(float& lo, float& hi, u64 v) {
    asm("mov.b64 {%0, %1}, %2;" : "=f"(lo), "=f"(hi) : "l"(v));
}
__device__ __forceinline__ u64 f2add(u64 a, u64 b) {
    u64 r; asm("add.rn.f32x2 %0, %1, %2;" : "=l"(r) : "l"(a), "l"(b)); return r;
}
__device__ __forceinline__ u64 f2mul(u64 a, u64 b) {
    u64 r; asm("mul.rn.f32x2 %0, %1, %2;" : "=l"(r) : "l"(a), "l"(b)); return r;
}

__global__ void __launch_bounds__(TPB, 1) __cluster_dims__(CLUSTER, 1, 1)
fps_kernel(const float* __restrict__ x, float* __restrict__ out)
{
    __shared__ u64 s_wkey[TPB / 32];        // per-warp winners
    __shared__ u64 s_cand[2][CLUSTER];      // double-buffered cluster candidates

    const u32 rank = cluster_rank();
    const int b    = blockIdx.x / CLUSTER;
    const int tid  = threadIdx.x;
    const int lane = tid & 31;
    const int warp = tid >> 5;
    const int tcl  = (int)rank * TPB + tid;                // 0..2047 within batch

    const float* __restrict__ xb = x + (size_t)b * 3 * NPTS;
    float* __restrict__ ob       = out + (size_t)b * 3 * MOUT;

    // Register-resident points (packed pairs) + running min distance
    u64 px2[PAIRS], py2[PAIRS], pz2[PAIRS];
    float dist[PPT];
#pragma unroll
    for (int i = 0; i < PAIRS; i++) {
        int k0 = 2 * i, k1 = 2 * i + 1;
        int g0 = k0 * TPBATCH + tcl, g1 = k1 * TPBATCH + tcl;   // coalesced
        px2[i] = f2pack(__ldg(xb + g0),            __ldg(xb + g1));
        py2[i] = f2pack(__ldg(xb + NPTS + g0),     __ldg(xb + NPTS + g1));
        pz2[i] = f2pack(__ldg(xb + 2 * NPTS + g0), __ldg(xb + 2 * NPTS + g1));
        dist[k0] = INFINITY;
        dist[k1] = INFINITY;
    }

    // First centroid is point 0 (standard PointNet++ convention)
    float cx = __ldg(xb);
    float cy = __ldg(xb + NPTS);
    float cz = __ldg(xb + 2 * NPTS);
    if (rank == 0 && tid == 0) {
        ob[0]        = cx;
        ob[MOUT]     = cy;
        ob[2 * MOUT] = cz;
    }

    for (int j = 1; j < MOUT; j++) {
        // ---- pass 1: packed distance update. Per-lane .rn arithmetic, same
        //      order as reference: (dx*dx + dy*dy) + dz*dz. Track max only
        //      (single serial fmax chain: R13 showed splitting it regresses). ----
        u64 ncx = f2pack(-cx, -cx);
        u64 ncy = f2pack(-cy, -cy);
        u64 ncz = f2pack(-cz, -cz);
        float best = -1.0f;
#pragma unroll
        for (int i = 0; i < PAIRS; i++) {
            u64 dx = f2add(px2[i], ncx);
            u64 dy = f2add(py2[i], ncy);
            u64 dz = f2add(pz2[i], ncz);
            u64 s  = f2add(f2mul(dx, dx), f2mul(dy, dy));
            u64 dd = f2add(s, f2mul(dz, dz));
            float e0, e1;
            f2unpack(e0, e1, dd);
            float n0 = fminf(dist[2 * i],     e0);
            float n1 = fminf(dist[2 * i + 1], e1);
            dist[2 * i]     = n0;
            dist[2 * i + 1] = n1;
            best = fmaxf(best, fmaxf(n0, n1));
        }

        // ---- pass 2: min k among dist[k]==best (first-occurrence argmax) ----
        int kb = 0x7FFFFFFF;
#pragma unroll
        for (int k = 0; k < PPT; k++) {
            if (dist[k] == best) kb = min(kb, k);
        }
        u32 bidx = (u32)(kb * TPBATCH + tcl);

        // ---- warp reduce via REDUX (R6/R10-proven numerics, ~half the serial
        //      latency of the 5-stage u64 shuffle chain): max dist bits (sq
        //      dists >= 0 so u32 order == float order), then min index among
        //      ties == jnp.argmax first-occurrence ----
        u32 dbits = __float_as_uint(best);
        u32 wmax  = __reduce_max_sync(0xFFFFFFFFu, dbits);
        u32 cnd   = (dbits == wmax) ? bidx : 0xFFFFFFFFu;
        u32 wmin  = __reduce_min_sync(0xFFFFFFFFu, cnd);
        if (lane == 0)
            s_wkey[warp] = ((u64)wmax << 32) | (u32)~wmin;   // key: dist | ~idx
        __syncthreads();

        // ---- block reduce (warp 0): REDUX over the 8 per-warp keys split
        //      hi/lo (max(~idx) == min idx among dist ties); lanes 0..7 fan
        //      the winner out to all 8 ranks in parallel ----
        if (warp == 0) {
            u64 k  = s_wkey[lane & 7];      // lanes 8-31 hold duplicates (harmless under max)
            u32 h  = (u32)(k >> 32);
            u32 lo = (u32)k;
            u32 hmax = __reduce_max_sync(0xFFFFFFFFu, h);
            u32 lsel = (h == hmax) ? lo : 0u;
            u32 lmax = __reduce_max_sync(0xFFFFFFFFu, lsel);
            if (lane < CLUSTER) {
                u64 bk = ((u64)hmax << 32) | lmax;
                u32 laddr = smem_u32(&s_cand[j & 1][rank]);
                u32 dst;
                asm volatile("mapa.shared::cluster.u32 %0, %1, %2;"
                             : "=r"(dst) : "r"(laddr), "r"((u32)lane));
                asm volatile("st.shared::cluster.u64 [%0], %1;"
                             :: "r"(dst), "l"(bk) : "memory");
            }
        }

        // ---- cluster barrier (arrive=release / wait=acquire orders the
        //      DSMEM stores above against the local reads below) ----
        cluster_sync_all();

        // ---- pick global winner from 8 local candidates (pairwise tree) ----
        {
            const u64* cand = s_cand[j & 1];
            u64 m0 = cand[0], m1 = cand[1], m2 = cand[2], m3 = cand[3];
            u64 m4 = cand[4], m5 = cand[5], m6 = cand[6], m7 = cand[7];
            u64 a = (m1 > m0) ? m1 : m0;
            u64 c = (m3 > m2) ? m3 : m2;
            u64 e = (m5 > m4) ? m5 : m4;
            u64 g = (m7 > m6) ? m7 : m6;
            u64 ac = (c > a) ? c : a;
            u64 eg = (g > e) ? g : e;
            u64 wk = (eg > ac) ? eg : ac;
            int widx = (int)(~(u32)wk);

            // ---- fetch winning centroid coords (L2-resident broadcast load) ----
            cx = __ldg(xb + widx);
            cy = __ldg(xb + NPTS + widx);
            cz = __ldg(xb + 2 * NPTS + widx);
        }

        if (rank == 0 && tid == 0) {
            ob[j]            = cx;
            ob[MOUT + j]     = cy;
            ob[2 * MOUT + j] = cz;
        }
    }
}

extern "C" void kernel_launch(void* const* d_in, const int* in_sizes, int n_in,
                              void* d_out, int out_size)
{
    const float* x = (const float*)d_in[0];
    float* out     = (float*)d_out;
    fps_kernel<<<BATCHES * CLUSTER, TPB>>>(x, out);
}

// round 15
// speedup vs baseline: 1.1332x; 1.0279x over previous
#include <cuda_runtime.h>
#include <cstdint>

// x (8, 3, 65536) f32 -> out (8, 3, 512) f32, farthest point sampling.
// R14 + flat 64-way cluster exchange (no intra-CTA funnel before the barrier).
#define BATCHES 8
#define NPTS    65536
#define MOUT    512
#define CLUSTER 8                         // CTAs per batch (one cluster)
#define TPB     256
#define NWARPS  (TPB / 32)                // 8 warps
#define TPBATCH (CLUSTER * TPB)           // 2048 threads per batch
#define PPT     (NPTS / TPBATCH)          // 32 points per thread (register-resident)
#define PAIRS   (PPT / 2)                 // 16 packed f32x2 pairs

typedef unsigned long long u64;
typedef unsigned int u32;

// ---- cluster helpers ----
__device__ __forceinline__ u32 cluster_rank() {
    u32 r; asm("mov.u32 %0, %%cluster_ctarank;" : "=r"(r)); return r;
}
__device__ __forceinline__ u32 smem_u32(const void* p) {
    return (u32)__cvta_generic_to_shared(p);
}
__device__ __forceinline__ void cluster_sync_all() {
    asm volatile("barrier.cluster.arrive.aligned;" ::: "memory");
    asm volatile("barrier.cluster.wait.aligned;"   ::: "memory");
}
// ---- packed f32x2 math (per-lane IEEE .rn, bit-identical to scalar) ----
__device__ __forceinline__ u64 f2pack(float lo, float hi) {
    u64 r; asm("mov.b64 %0, {%1, %2};" : "=l"(r) : "f"(lo), "f"(hi)); return r;
}
__device__ __forceinline__ void f2unpack(float& lo, float& hi, u64 v) {
    asm("mov.b64 {%0, %1}, %2;" : "=f"(lo), "=f"(hi) : "l"(v));
}
__device__ __forceinline__ u64 f2add(u64 a, u64 b) {
    u64 r; asm("add.rn.f32x2 %0, %1, %2;" : "=l"(r) : "l"(a), "l"(b)); return r;
}
__device__ __forceinline__ u64 f2mul(u64 a, u64 b) {
    u64 r; asm("mul.rn.f32x2 %0, %1, %2;" : "=l"(r) : "l"(a), "l"(b)); return r;
}

__global__ void __launch_bounds__(TPB, 1) __cluster_dims__(CLUSTER, 1, 1)
fps_kernel(const float* __restrict__ x, float* __restrict__ out)
{
    // [parity][src_rank][src_warp] warp-winner keys from the whole cluster.
    __shared__ __align__(16) u64 s_cand[2][CLUSTER][NWARPS];

    const u32 rank = cluster_rank();
    const int b    = blockIdx.x / CLUSTER;
    const int tid  = threadIdx.x;
    const int lane = tid & 31;
    const int warp = tid >> 5;
    const int tcl  = (int)rank * TPB + tid;                // 0..2047 within batch

    const float* __restrict__ xb = x + (size_t)b * 3 * NPTS;
    float* __restrict__ ob       = out + (size_t)b * 3 * MOUT;

    // Register-resident points (packed pairs) + running min distance
    u64 px2[PAIRS], py2[PAIRS], pz2[PAIRS];
    float dist[PPT];
#pragma unroll
    for (int i = 0; i < PAIRS; i++) {
        int k0 = 2 * i, k1 = 2 * i + 1;
        int g0 = k0 * TPBATCH + tcl, g1 = k1 * TPBATCH + tcl;   // coalesced
        px2[i] = f2pack(__ldg(xb + g0),            __ldg(xb + g1));
        py2[i] = f2pack(__ldg(xb + NPTS + g0),     __ldg(xb + NPTS + g1));
        pz2[i] = f2pack(__ldg(xb + 2 * NPTS + g0), __ldg(xb + 2 * NPTS + g1));
        dist[k0] = INFINITY;
        dist[k1] = INFINITY;
    }

    // First centroid is point 0 (standard PointNet++ convention)
    float cx = __ldg(xb);
    float cy = __ldg(xb + NPTS);
    float cz = __ldg(xb + 2 * NPTS);
    if (rank == 0 && tid == 0) {
        ob[0]        = cx;
        ob[MOUT]     = cy;
        ob[2 * MOUT] = cz;
    }

    for (int j = 1; j < MOUT; j++) {
        // ---- pass 1: packed distance update. Per-lane .rn arithmetic, same
        //      order as reference: (dx*dx + dy*dy) + dz*dz. Track max only. ----
        u64 ncx = f2pack(-cx, -cx);
        u64 ncy = f2pack(-cy, -cy);
        u64 ncz = f2pack(-cz, -cz);
        float best = -1.0f;
#pragma unroll
        for (int i = 0; i < PAIRS; i++) {
            u64 dx = f2add(px2[i], ncx);
            u64 dy = f2add(py2[i], ncy);
            u64 dz = f2add(pz2[i], ncz);
            u64 s  = f2add(f2mul(dx, dx), f2mul(dy, dy));
            u64 dd = f2add(s, f2mul(dz, dz));
            float e0, e1;
            f2unpack(e0, e1, dd);
            float n0 = fminf(dist[2 * i],     e0);
            float n1 = fminf(dist[2 * i + 1], e1);
            dist[2 * i]     = n0;
            dist[2 * i + 1] = n1;
            best = fmaxf(best, fmaxf(n0, n1));
        }

        // ---- pass 2: min k among dist[k]==best (first-occurrence argmax) ----
        int kb = 0x7FFFFFFF;
#pragma unroll
        for (int k = 0; k < PPT; k++) {
            if (dist[k] == best) kb = min(kb, k);
        }
        u32 bidx = (u32)(kb * TPBATCH + tcl);

        // ---- warp reduce via REDUX (R14-proven): max dist bits (sq dists
        //      >= 0 so u32 order == float order), then min index among ties
        //      == jnp.argmax first-occurrence. All lanes hold the result. ----
        u32 dbits = __float_as_uint(best);
        u32 wmax  = __reduce_max_sync(0xFFFFFFFFu, dbits);
        u32 cnd   = (dbits == wmax) ? bidx : 0xFFFFFFFFu;
        u32 wmin  = __reduce_min_sync(0xFFFFFFFFu, cnd);

        // ---- flat exchange: lanes 0..7 of EVERY warp store this warp's key
        //      into rank `lane`'s slot [my_rank][my_warp]. No __syncthreads,
        //      no block stage — straight to the cluster barrier. ----
        if (lane < CLUSTER) {
            u64 wkey = ((u64)wmax << 32) | (u32)~wmin;     // key: dist | ~idx
            u32 laddr = smem_u32(&s_cand[j & 1][rank][warp]);
            u32 dst;
            asm volatile("mapa.shared::cluster.u32 %0, %1, %2;"
                         : "=r"(dst) : "r"(laddr), "r"((u32)lane));
            asm volatile("st.shared::cluster.u64 [%0], %1;"
                         :: "r"(dst), "l"(wkey) : "memory");
        }

        // ---- cluster barrier (arrive=release / wait=acquire orders the
        //      DSMEM stores above against the local reads below) ----
        cluster_sync_all();

        // ---- each warp reduces all 64 cluster-wide warp winners itself:
        //      2 LDS per lane + pairwise max + hi/lo REDUX pair ----
        {
            const u64* cand = &s_cand[j & 1][0][0];
            u64 a = cand[lane];
            u64 c = cand[lane + 32];
            u64 m = (c > a) ? c : a;
            u32 h  = (u32)(m >> 32);
            u32 lo = (u32)m;
            u32 hmax = __reduce_max_sync(0xFFFFFFFFu, h);
            u32 lsel = (h == hmax) ? lo : 0u;              // max(~idx) == min idx
            u32 lmax = __reduce_max_sync(0xFFFFFFFFu, lsel);
            int widx = (int)(~lmax);

            // ---- fetch winning centroid coords (L2-resident broadcast load) ----
            cx = __ldg(xb + widx);
            cy = __ldg(xb + NPTS + widx);
            cz = __ldg(xb + 2 * NPTS + widx);
        }

        if (rank == 0 && tid == 0) {
            ob[j]            = cx;
            ob[MOUT + j]     = cy;
            ob[2 * MOUT + j] = cz;
        }
    }
}

extern "C" void kernel_launch(void* const* d_in, const int* in_sizes, int n_in,
                              void* d_out, int out_size)
{
    const float* x = (const float*)d_in[0];
    float* out     = (float*)d_out;
    fps_kernel<<<BATCHES * CLUSTER, TPB>>>(x, out);
}